// round 8
// baseline (speedup 1.0000x reference)
#include <cuda_runtime.h>
#include <cuda_bf16.h>

#define N 128
#define K 64
#define LLRMAX 100.0f
#define NPAT 2080   // 64 singles + 2016 pairs (t=2)

typedef unsigned long long u64;
typedef unsigned int u32;
typedef unsigned short u16;

__device__ __forceinline__ u32 mono(float s) {
    u32 u = __float_as_uint(s);
    return (u & 0x80000000u) ? ~u : (u | 0x80000000u);
}

__device__ __forceinline__ void decode_pair(int r, int& pi, int& pj) {
    int i = (int)((127.0f - sqrtf(16129.0f - 8.0f * (float)r)) * 0.5f);
    if (i < 0) i = 0; if (i > 62) i = 62;
    while (i * (127 - i) / 2 > r) i--;
    while ((i + 1) * (126 - i) / 2 <= r) i++;
    pi = i;
    pj = i + 1 + (r - i * (127 - i) / 2);
}

__global__ __launch_bounds__(512, 1)
void osd_kernel(const float* __restrict__ llrs,
                const float* __restrict__ gm,
                float* __restrict__ out)
{
    const int b    = blockIdx.x;
    const int tid  = threadIdx.x;
    const int lane = tid & 31;
    const int warp = tid >> 5;

    __shared__ __align__(16) float sLLR[N];
    __shared__ __align__(16) u64   sKey[N];
    __shared__ __align__(16) int   sIdxArr[N];
    __shared__ u32   sRP[4][N];              // rank partials (quarters)
    __shared__ u64   sP[K];                  // packed P rows (orig col order)
    __shared__ u32   sW[4][K];               // permuted-row quarters
    __shared__ u64   rloS[K], rhiS[K];       // reduced GF(2) rows
    __shared__ int   sPivArr[K];
    __shared__ u64   sPmLo, sPmHi;
    __shared__ __align__(16) int sMrbS[N];
    __shared__ float sLlrMrbS[N];
    __shared__ int   sTotS[N];
    __shared__ __align__(8) u64 sPPv[K];     // parity row, written as 4 u16 pieces
    __shared__ u64   sProwS[K];
    __shared__ unsigned char sUS[K];
    __shared__ u64   sCparPart[2];
    __shared__ float sSm[K];
    __shared__ float sLUT[8 * 256];
    __shared__ u64   sRed[16];

    // ===== Phase A: tid<128 loads llr+keys; warps 4-15 pack P =====
    if (tid < 128) {
        float x = llrs[b * N + tid];
        x = fminf(fmaxf(x, -LLRMAX), LLRMAX);
        sLLR[tid] = x;
        u32 ab = __float_as_uint(fabsf(x));
        // ascending key => descending |llr|, tie -> smaller original idx
        sKey[tid] = (((u64)(ab ^ 0xFFFFFFFFu)) << 8) | (u32)tid;
    }
    if (warp >= 4) {
        for (int r = warp - 4; r < K; r += 12) {
            float f0 = gm[r * N + 64 + lane];
            float f1 = gm[r * N + 96 + lane];
            u32 b0 = __ballot_sync(0xFFFFFFFFu, f0 != 0.0f);
            u32 b1 = __ballot_sync(0xFFFFFFFFu, f1 != 0.0f);
            if (lane == 0) sP[r] = (u64)b0 | ((u64)b1 << 32);
        }
    }
    __syncthreads();   // bar1

    // ===== Rank sort: 4 threads per element, 32 compares each =====
    {
        int e = tid & 127, q = tid >> 7;       // q in 0..3
        u64 my = sKey[e];
        const u64* base = sKey + (q << 5);
        int cnt = 0;
        #pragma unroll
        for (int o = 0; o < 32; o++)
            cnt += (base[o] < my);
        sRP[q][e] = (u32)cnt;
    }
    __syncthreads();   // bar2

    if (tid < 128) {
        int rank = sRP[0][tid] + sRP[1][tid] + sRP[2][tid] + sRP[3][tid];
        sIdxArr[rank] = tid;
    }
    __syncthreads();   // bar3

    // ===== Phase B: permuted rows, 4 threads/row (u32 quarters) =====
    if (tid < 256) {
        int row = tid & 63, q = tid >> 6;      // q in 0..3
        u64 myP = sP[row];
        u32 w = 0u;
        const int4* v = (const int4*)(sIdxArr + (q << 5));
        #pragma unroll
        for (int t = 0; t < 8; t++) {
            int4 c4 = v[t];
            int j = t << 2;
            u32 b0 = (c4.x >= 64) ? (u32)((myP >> (c4.x - 64)) & 1ull) : (u32)(c4.x == row);
            u32 b1 = (c4.y >= 64) ? (u32)((myP >> (c4.y - 64)) & 1ull) : (u32)(c4.y == row);
            u32 b2 = (c4.z >= 64) ? (u32)((myP >> (c4.z - 64)) & 1ull) : (u32)(c4.z == row);
            u32 b3 = (c4.w >= 64) ? (u32)((myP >> (c4.w - 64)) & 1ull) : (u32)(c4.w == row);
            w |= (b0 << j) | (b1 << (j + 1)) | (b2 << (j + 2)) | (b3 << (j + 3));
        }
        sW[q][row] = w;
    }
    __syncthreads();   // bar4

    // ===== Phase C: GF(2) elimination (warp0, rows 2l/2l+1 per lane) =====
    if (warp == 0) {
        int r0 = 2 * lane, r1 = 2 * lane + 1;
        u64 a0lo = (u64)sW[0][r0] | ((u64)sW[1][r0] << 32);
        u64 a0hi = (u64)sW[2][r0] | ((u64)sW[3][r0] << 32);
        u64 a1lo = (u64)sW[0][r1] | ((u64)sW[1][r1] << 32);
        u64 a1hi = (u64)sW[2][r1] | ((u64)sW[3][r1] << 32);
        u64 pmLo = 0ull, pmHi = 0ull;
        #pragma unroll 1
        for (int i = 0; i < 64; i += 2) {
            int src = i >> 1;
            {   // even step: pivot row i = a0 of lane src
                u64 plo = __shfl_sync(0xFFFFFFFFu, a0lo, src);
                u64 phi = __shfl_sync(0xFFFFFFFFu, a0hi, src);
                int p = plo ? (__ffsll((long long)plo) - 1)
                            : 64 + (__ffsll((long long)phi) - 1);
                if (lane == 0) {
                    sPivArr[i] = p;
                    if (p < 64) pmLo |= 1ull << p; else pmHi |= 1ull << (p - 64);
                }
                int sh = p & 63;
                bool h0 = (((p < 64) ? a0lo : a0hi) >> sh) & 1ull;
                bool h1 = (((p < 64) ? a1lo : a1hi) >> sh) & 1ull;
                if (h0 && lane != src)  { a0lo ^= plo; a0hi ^= phi; }
                if (h1)                 { a1lo ^= plo; a1hi ^= phi; }
            }
            {   // odd step: pivot row i+1 = a1 of lane src
                u64 plo = __shfl_sync(0xFFFFFFFFu, a1lo, src);
                u64 phi = __shfl_sync(0xFFFFFFFFu, a1hi, src);
                int p = plo ? (__ffsll((long long)plo) - 1)
                            : 64 + (__ffsll((long long)phi) - 1);
                if (lane == 0) {
                    sPivArr[i + 1] = p;
                    if (p < 64) pmLo |= 1ull << p; else pmHi |= 1ull << (p - 64);
                }
                int sh = p & 63;
                bool h0 = (((p < 64) ? a0lo : a0hi) >> sh) & 1ull;
                bool h1 = (((p < 64) ? a1lo : a1hi) >> sh) & 1ull;
                if (h0)                 { a0lo ^= plo; a0hi ^= phi; }
                if (h1 && lane != src)  { a1lo ^= plo; a1hi ^= phi; }
            }
        }
        rloS[r0] = a0lo; rhiS[r0] = a0hi;
        rloS[r1] = a1lo; rhiS[r1] = a1hi;
        if (lane == 0) { sPmLo = pmLo; sPmHi = pmHi; }
    }
    __syncthreads();   // bar5

    // ===== Phase D: idx_mrb + gathers (+ fused sUS / sSm) =====
    if (tid < 128) {
        int m;
        if (tid < K) {
            m = sPivArr[tid];
        } else {
            int t = tid - K;
            u64 zlo = ~sPmLo, zhi = ~sPmHi;
            int nlo = __popcll(zlo);
            u64 x; int base;
            if (t < nlo) { x = zlo; base = 0; }
            else         { x = zhi; base = 64; t -= nlo; }
            int pos = 0;
            #pragma unroll
            for (int byteI = 0; byteI < 8; byteI++) {
                u32 bb = (u32)(x >> (byteI * 8)) & 0xFFu;
                int c = __popc(bb);
                if (t < c) {
                    while (t > 0) { bb &= bb - 1; t--; }
                    pos = byteI * 8 + (__ffs(bb) - 1);
                    break;
                }
                t -= c;
            }
            m = base + pos;
        }
        sMrbS[tid] = m;
        int oc = sIdxArr[m];
        float x = sLLR[oc];
        sLlrMrbS[tid] = x;
        sTotS[tid]    = oc;
        if (tid < K) {
            int u = (x > 0.0f) ? 1 : 0;
            sUS[tid] = (unsigned char)u;
            sSm[tid] = u ? -x : x;
        }
    }
    __syncthreads();   // bar6

    // ===== Phase E1: parity pieces, 4 threads/row (u16 each) =====
    if (tid < 256) {
        int row = tid & 63, q = tid >> 6;      // q in 0..3
        u64 lo = rloS[row], hi = rhiS[row];
        u32 pr = 0u;
        int p0 = q << 4;
        const int4* v = (const int4*)(sMrbS + 64 + p0);
        #pragma unroll
        for (int t = 0; t < 4; t++) {
            int4 c4 = v[t];
            int p = t << 2;
            u32 b0 = (u32)((c4.x < 64) ? ((lo >> c4.x) & 1ull) : ((hi >> (c4.x - 64)) & 1ull));
            u32 b1 = (u32)((c4.y < 64) ? ((lo >> c4.y) & 1ull) : ((hi >> (c4.y - 64)) & 1ull));
            u32 b2 = (u32)((c4.z < 64) ? ((lo >> c4.z) & 1ull) : ((hi >> (c4.z - 64)) & 1ull));
            u32 b3 = (u32)((c4.w < 64) ? ((lo >> c4.w) & 1ull) : ((hi >> (c4.w - 64)) & 1ull));
            pr |= (b0 << p) | (b1 << (p + 1)) | (b2 << (p + 2)) | (b3 << (p + 3));
        }
        ((u16*)&sPPv[row])[q] = (u16)pr;
    }
    __syncthreads();   // bar7

    // ===== Phase E2: base parity reduce (threads 0..63) =====
    if (tid < K) {
        u64 pr = sPPv[tid];
        sProwS[tid] = pr;
        u64 val = sUS[tid] ? pr : 0ull;
        #pragma unroll
        for (int o = 16; o > 0; o >>= 1)
            val ^= __shfl_xor_sync(0xFFFFFFFFu, val, o);
        if (lane == 0) sCparPart[warp] = val;
    }
    __syncthreads();   // bar8

    const u64 cpar = sCparPart[0] ^ sCparPart[1];

    // ===== Phase F: LUT build (4 entries/thread), signs inline from cpar =====
    #pragma unroll
    for (int e = 0; e < 4; e++) {
        int idx2 = tid + (e << 9);          // 0..2047
        int ci = idx2 >> 8;
        int v  = idx2 & 255;
        float s = 0.0f;
        #pragma unroll
        for (int bb = 0; bb < 8; bb++) {
            int p = ci * 8 + bb;
            float x = sLlrMrbS[64 + p];
            float sv = ((cpar >> p) & 1ull) ? -x : x;
            if ((v >> bb) & 1) s += sv;
        }
        sLUT[idx2] = s;
    }
    __syncthreads();   // bar9

    // ===== Phase G: candidate search (512 threads, 4-5 patterns each) =====
    int id, cnt;
    if (tid < 32) { id = tid * 5;              cnt = 5; }
    else          { id = 160 + (tid - 32) * 4; cnt = 4; }

    int pi = 0, pj = 0;
    if (id >= 64 && id < NPAT) decode_pair(id - 64, pi, pj);

    u64 bestKey = (((u64)mono(0.0f)) << 32) | (u32)(NPAT + 1);   // base codeword
    for (int e = 0; e < cnt && id < NPAT; e++) {
        u64 m; float S;
        if (id < 64) { m = sProwS[id];              S = sSm[id]; }
        else         { m = sProwS[pi] ^ sProwS[pj]; S = sSm[pi] + sSm[pj]; }
        #pragma unroll
        for (int cc = 0; cc < 8; cc++)
            S += sLUT[(cc << 8) | ((int)(m >> (cc * 8)) & 0xFF)];
        u64 keyv = (((u64)mono(S)) << 32) | (u32)(NPAT - id);
        if (keyv > bestKey) bestKey = keyv;
        id++;
        if (id == 64)     { pi = 0; pj = 1; }
        else if (id > 64) { pj++; if (pj == 64) { pi++; pj = pi + 1; } }
    }
    #pragma unroll
    for (int o = 16; o > 0; o >>= 1) {
        u64 other = __shfl_xor_sync(0xFFFFFFFFu, bestKey, o);
        if (other > bestKey) bestKey = other;
    }
    if (lane == 0) sRed[warp] = bestKey;
    __syncthreads();   // bar10

    // ===== Phase H: decode winner + emit (tid<128) =====
    if (tid < 128) {
        u64 bk = sRed[0];
        #pragma unroll
        for (int w = 1; w < 16; w++) if (sRed[w] > bk) bk = sRed[w];
        int wid2 = NPAT - (int)(bk & 0xFFFFFFFFull);   // -1 = base
        int fi = -1, fj = -1;
        if (wid2 >= 0) {
            if (wid2 < 64) fi = wid2;
            else           decode_pair(wid2 - 64, fi, fj);
        }
        int j = tid;
        int cj = (j < 64) ? (int)sUS[j] : (int)((cpar >> (j - 64)) & 1ull);
        if (j < 64) {
            if (j == fi) cj ^= 1;
            if (j == fj) cj ^= 1;
        } else {
            int p = j - 64;
            if (fi >= 0) cj ^= (int)((sProwS[fi] >> p) & 1ull);
            if (fj >= 0) cj ^= (int)((sProwS[fj] >> p) & 1ull);
        }
        out[b * N + sTotS[j]] = (float)cj;
    }
}

extern "C" void kernel_launch(void* const* d_in, const int* in_sizes, int n_in,
                              void* d_out, int out_size)
{
    const float* llrs = (const float*)d_in[0];
    const float* gm   = (const float*)d_in[1];
    float* out        = (float*)d_out;
    int bs = in_sizes[0] / N;   // 128
    osd_kernel<<<bs, 512>>>(llrs, gm, out);
}

// round 9
// speedup vs baseline: 1.0363x; 1.0363x over previous
#include <cuda_runtime.h>
#include <cuda_bf16.h>

#define N 128
#define K 64
#define LLRMAX 100.0f
#define NPAT 2080   // 64 singles + 2016 pairs (t=2)

typedef unsigned long long u64;
typedef unsigned int u32;
typedef unsigned short u16;

__device__ __forceinline__ u32 mono(float s) {
    u32 u = __float_as_uint(s);
    return (u & 0x80000000u) ? ~u : (u | 0x80000000u);
}

__device__ __forceinline__ void decode_pair(int r, int& pi, int& pj) {
    int i = (int)((127.0f - sqrtf(16129.0f - 8.0f * (float)r)) * 0.5f);
    if (i < 0) i = 0; if (i > 62) i = 62;
    while (i * (127 - i) / 2 > r) i--;
    while ((i + 1) * (126 - i) / 2 <= r) i++;
    pi = i;
    pj = i + 1 + (r - i * (127 - i) / 2);
}

__global__ __launch_bounds__(256, 1)
void osd_kernel(const float* __restrict__ llrs,
                const float* __restrict__ gm,
                float* __restrict__ out)
{
    const int b    = blockIdx.x;
    const int tid  = threadIdx.x;
    const int lane = tid & 31;
    const int warp = tid >> 5;

    __shared__ __align__(16) float sLLR[N];
    __shared__ __align__(16) u64   sKey[N];
    __shared__ __align__(16) int   sIdxArr[N];
    __shared__ int   sRankArr[N];
    __shared__ u64   sP[K];                  // packed P rows (orig col order)
    __shared__ u32   sW[4][K];               // permuted-row quarters
    __shared__ u64   rloS[K], rhiS[K];       // reduced GF(2) rows
    __shared__ int   sPivArr[K];
    __shared__ u64   sPmLo, sPmHi;
    __shared__ __align__(16) int sMrbS[N];
    __shared__ float sLlrMrbS[N];
    __shared__ int   sTotS[N];
    __shared__ __align__(8) u64 sPPv[K];     // parity row, 4 u16 pieces
    __shared__ u64   sProwS[K];
    __shared__ unsigned char sUS[K];
    __shared__ u64   sCparPart[2];
    __shared__ float sSm[K];
    __shared__ float sLUT[8 * 256];
    __shared__ u64   sRed[8];

    // ===== Phase A: tid<128 loads llr+keys; warps 4-7 pack P (MLP preload) =====
    if (tid < 128) {
        float x = llrs[b * N + tid];
        x = fminf(fmaxf(x, -LLRMAX), LLRMAX);
        sLLR[tid] = x;
        u32 ab = __float_as_uint(fabsf(x));
        // ascending key => descending |llr|, tie -> smaller original idx
        sKey[tid] = (((u64)(ab ^ 0xFFFFFFFFu)) << 8) | (u32)tid;
    }
    if (warp >= 4) {
        int r0 = (warp - 4) << 4;
        float f0[16], f1[16];
        #pragma unroll
        for (int q = 0; q < 16; q++) {
            f0[q] = gm[(r0 + q) * N + 64 + lane];
            f1[q] = gm[(r0 + q) * N + 96 + lane];
        }
        #pragma unroll
        for (int q = 0; q < 16; q++) {
            u32 b0 = __ballot_sync(0xFFFFFFFFu, f0[q] != 0.0f);
            u32 b1 = __ballot_sync(0xFFFFFFFFu, f1[q] != 0.0f);
            if (lane == 0) sP[r0 + q] = (u64)b0 | ((u64)b1 << 32);
        }
    }
    __syncthreads();   // bar1

    // ===== Rank sort: 1 thread/element, vectorized compares (overlaps pack tail) =====
    if (tid < 128) {
        u64 my = sKey[tid];
        const ulonglong2* kp = (const ulonglong2*)sKey;
        int cnt = 0;
        #pragma unroll
        for (int o = 0; o < 64; o++) {
            ulonglong2 kk = kp[o];
            cnt += (int)(kk.x < my) + (int)(kk.y < my);
        }
        sIdxArr[cnt]  = tid;
        sRankArr[tid] = cnt;
    }
    __syncthreads();   // bar2

    // ===== Phase B: permuted rows, 4 threads/row (u32 quarters), P-part only =====
    {
        int row = tid & 63, q = tid >> 6;      // q in 0..3
        u64 myP = sP[row];
        u32 w = 0u;
        const int4* v = (const int4*)(sIdxArr + (q << 5));
        #pragma unroll
        for (int t = 0; t < 8; t++) {
            int4 c4 = v[t];
            int j = t << 2;
            u32 b0 = ((u32)(c4.x - 64) < 64u) ? (u32)((myP >> (c4.x - 64)) & 1ull) : 0u;
            u32 b1 = ((u32)(c4.y - 64) < 64u) ? (u32)((myP >> (c4.y - 64)) & 1ull) : 0u;
            u32 b2 = ((u32)(c4.z - 64) < 64u) ? (u32)((myP >> (c4.z - 64)) & 1ull) : 0u;
            u32 b3 = ((u32)(c4.w - 64) < 64u) ? (u32)((myP >> (c4.w - 64)) & 1ull) : 0u;
            w |= (b0 << j) | (b1 << (j + 1)) | (b2 << (j + 2)) | (b3 << (j + 3));
        }
        int rk = sRankArr[row];                // identity column of this row
        if ((rk >> 5) == q) w |= 1u << (rk & 31);
        sW[q][row] = w;
    }
    __syncthreads();   // bar3

    // ===== Phase C: GF(2) elimination (warp0, rows 2l/2l+1 per lane) =====
    if (warp == 0) {
        int r0 = 2 * lane, r1 = 2 * lane + 1;
        u64 a0lo = (u64)sW[0][r0] | ((u64)sW[1][r0] << 32);
        u64 a0hi = (u64)sW[2][r0] | ((u64)sW[3][r0] << 32);
        u64 a1lo = (u64)sW[0][r1] | ((u64)sW[1][r1] << 32);
        u64 a1hi = (u64)sW[2][r1] | ((u64)sW[3][r1] << 32);
        u64 pmLo = 0ull, pmHi = 0ull;
        #pragma unroll 1
        for (int i = 0; i < 64; i += 2) {
            int src = i >> 1;
            {   // pivot row i = a0 of lane src
                u64 plo = __shfl_sync(0xFFFFFFFFu, a0lo, src);
                u64 phi = __shfl_sync(0xFFFFFFFFu, a0hi, src);
                int p = plo ? (__ffsll((long long)plo) - 1)
                            : 64 + (__ffsll((long long)phi) - 1);
                if (lane == 0) {
                    sPivArr[i] = p;
                    if (p < 64) pmLo |= 1ull << p; else pmHi |= 1ull << (p - 64);
                }
                int sh = p & 63;
                bool h0 = (((p < 64) ? a0lo : a0hi) >> sh) & 1ull;
                bool h1 = (((p < 64) ? a1lo : a1hi) >> sh) & 1ull;
                if (h0 && lane != src)  { a0lo ^= plo; a0hi ^= phi; }
                if (h1)                 { a1lo ^= plo; a1hi ^= phi; }
            }
            {   // pivot row i+1 = a1 of lane src
                u64 plo = __shfl_sync(0xFFFFFFFFu, a1lo, src);
                u64 phi = __shfl_sync(0xFFFFFFFFu, a1hi, src);
                int p = plo ? (__ffsll((long long)plo) - 1)
                            : 64 + (__ffsll((long long)phi) - 1);
                if (lane == 0) {
                    sPivArr[i + 1] = p;
                    if (p < 64) pmLo |= 1ull << p; else pmHi |= 1ull << (p - 64);
                }
                int sh = p & 63;
                bool h0 = (((p < 64) ? a0lo : a0hi) >> sh) & 1ull;
                bool h1 = (((p < 64) ? a1lo : a1hi) >> sh) & 1ull;
                if (h0)                 { a0lo ^= plo; a0hi ^= phi; }
                if (h1 && lane != src)  { a1lo ^= plo; a1hi ^= phi; }
            }
        }
        rloS[r0] = a0lo; rhiS[r0] = a0hi;
        rloS[r1] = a1lo; rhiS[r1] = a1hi;
        if (lane == 0) { sPmLo = pmLo; sPmHi = pmHi; }
    }
    __syncthreads();   // bar4

    // ===== Phase D: idx_mrb + gathers (+ fused sUS / sSm) =====
    if (tid < 128) {
        int m;
        if (tid < K) {
            m = sPivArr[tid];
        } else {
            int t = tid - K;
            u64 zlo = ~sPmLo, zhi = ~sPmHi;
            int nlo = __popcll(zlo);
            u64 x; int base;
            if (t < nlo) { x = zlo; base = 0; }
            else         { x = zhi; base = 64; t -= nlo; }
            int pos = 0;
            #pragma unroll
            for (int byteI = 0; byteI < 8; byteI++) {
                u32 bb = (u32)(x >> (byteI * 8)) & 0xFFu;
                int c = __popc(bb);
                if (t < c) {
                    while (t > 0) { bb &= bb - 1; t--; }
                    pos = byteI * 8 + (__ffs(bb) - 1);
                    break;
                }
                t -= c;
            }
            m = base + pos;
        }
        sMrbS[tid] = m;
        int oc = sIdxArr[m];
        float x = sLLR[oc];
        sLlrMrbS[tid] = x;
        sTotS[tid]    = oc;
        if (tid < K) {
            int u = (x > 0.0f) ? 1 : 0;
            sUS[tid] = (unsigned char)u;
            sSm[tid] = u ? -x : x;
        }
    }
    __syncthreads();   // bar5

    // ===== Phase E1: parity pieces, 4 threads/row (u16 each) =====
    {
        int row = tid & 63, q = tid >> 6;      // q in 0..3
        u64 lo = rloS[row], hi = rhiS[row];
        u32 pr = 0u;
        int p0 = q << 4;
        const int4* v = (const int4*)(sMrbS + 64 + p0);
        #pragma unroll
        for (int t = 0; t < 4; t++) {
            int4 c4 = v[t];
            int p = t << 2;
            u32 b0 = (u32)((c4.x < 64) ? ((lo >> c4.x) & 1ull) : ((hi >> (c4.x - 64)) & 1ull));
            u32 b1 = (u32)((c4.y < 64) ? ((lo >> c4.y) & 1ull) : ((hi >> (c4.y - 64)) & 1ull));
            u32 b2 = (u32)((c4.z < 64) ? ((lo >> c4.z) & 1ull) : ((hi >> (c4.z - 64)) & 1ull));
            u32 b3 = (u32)((c4.w < 64) ? ((lo >> c4.w) & 1ull) : ((hi >> (c4.w - 64)) & 1ull));
            pr |= (b0 << p) | (b1 << (p + 1)) | (b2 << (p + 2)) | (b3 << (p + 3));
        }
        ((u16*)&sPPv[row])[q] = (u16)pr;
    }
    __syncthreads();   // bar6

    // ===== Phase E2: base parity reduce (threads 0..63) =====
    if (tid < K) {
        u64 pr = sPPv[tid];
        sProwS[tid] = pr;
        u64 val = sUS[tid] ? pr : 0ull;
        #pragma unroll
        for (int o = 16; o > 0; o >>= 1)
            val ^= __shfl_xor_sync(0xFFFFFFFFu, val, o);
        if (lane == 0) sCparPart[warp] = val;
    }
    __syncthreads();   // bar7

    const u64 cpar = sCparPart[0] ^ sCparPart[1];

    // ===== Phase F: LUT build — warp-per-chunk, register DP (8 entries/thread) =====
    {
        int ci = warp;            // chunk 0..7 (uniform per warp)
        float sv[8];
        #pragma unroll
        for (int bb = 0; bb < 8; bb++) {
            int p = ci * 8 + bb;
            float x = sLlrMrbS[64 + p];               // broadcast LDS
            sv[bb] = ((cpar >> p) & 1ull) ? -x : x;
        }
        // base: sum of low-5 bits from lane
        float base = 0.0f;
        #pragma unroll
        for (int bb = 0; bb < 5; bb++)
            if ((lane >> bb) & 1) base += sv[bb];
        // DP over bits 5,6,7
        float h5 = sv[5], h6 = sv[6], h7 = sv[7];
        float s56 = h5 + h6, s57 = h5 + h7, s67 = h6 + h7, s567 = s56 + h7;
        float hsum[8] = {0.0f, h5, h6, s56, h7, s57, s67, s567};
        float* dst = sLUT + (ci << 8) + lane;
        #pragma unroll
        for (int e = 0; e < 8; e++)
            dst[e << 5] = base + hsum[e];
    }
    __syncthreads();   // bar8

    // ===== Phase G: candidate search =====
    int id, cnt;
    if (tid < 32) { id = tid * 9;              cnt = 9; }
    else          { id = 288 + (tid - 32) * 8; cnt = 8; }

    int pi = 0, pj = 0;
    if (id >= 64 && id < NPAT) decode_pair(id - 64, pi, pj);

    float bestS = 0.0f;          // base codeword score
    int   bestId = -1;
    for (int e = 0; e < cnt && id < NPAT; e++) {
        u64 m; float S;
        if (id < 64) { m = sProwS[id];              S = sSm[id]; }
        else         { m = sProwS[pi] ^ sProwS[pj]; S = sSm[pi] + sSm[pj]; }
        #pragma unroll
        for (int cc = 0; cc < 8; cc++)
            S += sLUT[(cc << 8) | ((int)(m >> (cc * 8)) & 0xFF)];
        if (S > bestS) { bestS = S; bestId = id; }   // ids ascending -> first max kept
        id++;
        if (id == 64)     { pi = 0; pj = 1; }
        else if (id > 64) { pj++; if (pj == 64) { pi++; pj = pi + 1; } }
    }
    u64 bestKey = (((u64)mono(bestS)) << 32) | (u32)(NPAT - bestId);
    #pragma unroll
    for (int o = 16; o > 0; o >>= 1) {
        u64 other = __shfl_xor_sync(0xFFFFFFFFu, bestKey, o);
        if (other > bestKey) bestKey = other;
    }
    if (lane == 0) sRed[warp] = bestKey;
    __syncthreads();   // bar9

    // ===== Phase H: decode winner + emit =====
    if (tid < 128) {
        u64 bk = sRed[0];
        #pragma unroll
        for (int w = 1; w < 8; w++) if (sRed[w] > bk) bk = sRed[w];
        int wid2 = NPAT - (int)(bk & 0xFFFFFFFFull);   // -1 = base
        int fi = -1, fj = -1;
        if (wid2 >= 0) {
            if (wid2 < 64) fi = wid2;
            else           decode_pair(wid2 - 64, fi, fj);
        }
        int j = tid;
        int cj = (j < 64) ? (int)sUS[j] : (int)((cpar >> (j - 64)) & 1ull);
        if (j < 64) {
            if (j == fi) cj ^= 1;
            if (j == fj) cj ^= 1;
        } else {
            int p = j - 64;
            if (fi >= 0) cj ^= (int)((sProwS[fi] >> p) & 1ull);
            if (fj >= 0) cj ^= (int)((sProwS[fj] >> p) & 1ull);
        }
        out[b * N + sTotS[j]] = (float)cj;
    }
}

extern "C" void kernel_launch(void* const* d_in, const int* in_sizes, int n_in,
                              void* d_out, int out_size)
{
    const float* llrs = (const float*)d_in[0];
    const float* gm   = (const float*)d_in[1];
    float* out        = (float*)d_out;
    int bs = in_sizes[0] / N;   // 128
    osd_kernel<<<bs, 256>>>(llrs, gm, out);
}